// round 17
// baseline (speedup 1.0000x reference)
#include <cuda_runtime.h>
#include <cuda_fp16.h>
#include <mma.h>
#include <math.h>
#include <stdint.h>

using namespace nvcuda;

static const int MAXN = 50000;
static const int MAXE = 800000 + MAXN;

// ---------------- scratch ----------------
__device__ __half g_h1h[MAXN * 256];   // layer1 features, fp16
__device__ __half g_o1h[MAXN * 256];   // relu(layer1 out), fp16 (feeds GEMM2)
__device__ float  g_as1[MAXN * 8];
__device__ float  g_ad1[MAXN * 8];
__device__ __half g_h2h[MAXN * 32];    // layer2 features, fp16
__device__ float  g_as2[MAXN];
__device__ float  g_ad2[MAXN];
__device__ int    g_cnt[MAXN];
__device__ int    g_row[MAXN + 1];
__device__ int    g_cur[MAXN];
__device__ int    g_bsum[256];
__device__ int    g_boff[256];
__device__ int    g_esrc[MAXE];
__device__ __half g_xh[MAXN * 128];    // x in fp16
__device__ __half g_wth[256 * 128];    // W1^T fp16
__device__ __half g_w2t[32 * 256];     // W2^T fp16

__device__ __forceinline__ float lrelu(float v) { return v > 0.f ? v : 0.2f * v; }

// ================= GEMM1 wmma fp16 + fused alpha8, fp16 out =================
static const int LDM = 136;
static const int CLD = 132;
static const int WSM_TOTAL = 2 * 128 * LDM * 2;   // 69632

__global__ __launch_bounds__(512, 2)
void gemm1_wmma_k(const __half* __restrict__ xh, const __half* __restrict__ wth,
                  const float* __restrict__ aS1, const float* __restrict__ aD1,
                  __half* __restrict__ outh, float* __restrict__ as, float* __restrict__ ad,
                  int M) {
    extern __shared__ char smraw[];
    __half* Ah = (__half*)smraw;
    __half* Bh = Ah + 128 * LDM;
    float* Csf = (float*)smraw;
    int tid = threadIdx.x, wid = tid >> 5, lane = tid & 31;
    int m0 = blockIdx.y * 128, n0 = blockIdx.x * 128;

    for (int idx = tid; idx < 128 * 16; idx += 512) {
        int r = idx >> 4, c = idx & 15;
        uint4 v = make_uint4(0u, 0u, 0u, 0u);
        if (m0 + r < M) v = ((const uint4*)xh)[(size_t)(m0 + r) * 16 + c];
        ((uint4*)(Ah + r * LDM))[c] = v;
    }
    for (int idx = tid; idx < 128 * 16; idx += 512) {
        int r = idx >> 4, c = idx & 15;
        ((uint4*)(Bh + r * LDM))[c] = ((const uint4*)wth)[(size_t)(n0 + r) * 16 + c];
    }
    __syncthreads();

    int wr = wid & 3, wc = wid >> 2;
    wmma::fragment<wmma::accumulator, 16, 16, 16, float> acc[2][2];
    #pragma unroll
    for (int i = 0; i < 2; i++)
        #pragma unroll
        for (int j = 0; j < 2; j++) wmma::fill_fragment(acc[i][j], 0.f);

    #pragma unroll
    for (int k = 0; k < 128; k += 16) {
        wmma::fragment<wmma::matrix_a, 16, 16, 16, __half, wmma::row_major> af[2];
        wmma::fragment<wmma::matrix_b, 16, 16, 16, __half, wmma::col_major> bf[2];
        #pragma unroll
        for (int i = 0; i < 2; i++)
            wmma::load_matrix_sync(af[i], Ah + (wr * 32 + i * 16) * LDM + k, LDM);
        #pragma unroll
        for (int j = 0; j < 2; j++)
            wmma::load_matrix_sync(bf[j], Bh + (wc * 32 + j * 16) * LDM + k, LDM);
        #pragma unroll
        for (int i = 0; i < 2; i++)
            #pragma unroll
            for (int j = 0; j < 2; j++)
                wmma::mma_sync(acc[i][j], af[i], bf[j], acc[i][j]);
    }
    __syncthreads();

    #pragma unroll
    for (int i = 0; i < 2; i++)
        #pragma unroll
        for (int j = 0; j < 2; j++)
            wmma::store_matrix_sync(Csf + (wr * 32 + i * 16) * CLD + wc * 32 + j * 16,
                                    acc[i][j], CLD, wmma::mem_row_major);
    __syncthreads();

    // fused alpha8
    {
        int hb = n0 >> 5;
        int hl = lane >> 3, k4 = lane & 7;
        float4 cs = ((const float4*)aS1)[(hb + hl) * 8 + k4];
        float4 cd = ((const float4*)aD1)[(hb + hl) * 8 + k4];
        #pragma unroll
        for (int rr = 0; rr < 8; rr++) {
            int r = wid * 8 + rr;
            float4 v = *(float4*)&Csf[r * CLD + hl * 32 + k4 * 4];
            float ps = v.x * cs.x + v.y * cs.y + v.z * cs.z + v.w * cs.w;
            float pd = v.x * cd.x + v.y * cd.y + v.z * cd.z + v.w * cd.w;
            #pragma unroll
            for (int off = 4; off; off >>= 1) {
                ps += __shfl_xor_sync(0xffffffffu, ps, off);
                pd += __shfl_xor_sync(0xffffffffu, pd, off);
            }
            int gr = m0 + r;
            if (k4 == 0 && gr < M) {
                as[gr * 8 + hb + hl] = ps;
                ad[gr * 8 + hb + hl] = pd;
            }
        }
    }
    // h1 store as fp16
    for (int idx = tid; idx < 128 * 16; idx += 512) {
        int r = idx >> 4, c8 = idx & 15;
        if (m0 + r >= M) continue;
        float4 v0 = *(float4*)&Csf[r * CLD + c8 * 8];
        float4 v1 = *(float4*)&Csf[r * CLD + c8 * 8 + 4];
        __half2 p0 = __floats2half2_rn(v0.x, v0.y);
        __half2 p1 = __floats2half2_rn(v0.z, v0.w);
        __half2 p2 = __floats2half2_rn(v1.x, v1.y);
        __half2 p3 = __floats2half2_rn(v1.z, v1.w);
        uint4 pk;
        pk.x = *(unsigned*)&p0; pk.y = *(unsigned*)&p1;
        pk.z = *(unsigned*)&p2; pk.w = *(unsigned*)&p3;
        *(uint4*)(outh + (size_t)(m0 + r) * 256 + n0 + c8 * 8) = pk;
    }
}

// ================= GEMM2 wmma fp16 + fused alpha1, fp16 out =================
static const int G2LD = 72;

__global__ __launch_bounds__(256)
void gemm2_wmma_k(const __half* __restrict__ Ahg, const __half* __restrict__ w2t,
                  const float* __restrict__ aS2, const float* __restrict__ aD2,
                  __half* __restrict__ h2h, float* __restrict__ as2, float* __restrict__ ad2,
                  int M) {
    __shared__ __half As[128 * G2LD];
    __shared__ __half Bs[32 * G2LD];
    float* Csf = (float*)As;
    int tid = threadIdx.x, wid = tid >> 5;
    int m0 = blockIdx.x * 128;
    int wr = wid & 3, wc = wid >> 2;

    wmma::fragment<wmma::accumulator, 16, 16, 16, float> acc[2];
    wmma::fill_fragment(acc[0], 0.f);
    wmma::fill_fragment(acc[1], 0.f);

    for (int kc = 0; kc < 256; kc += 64) {
        #pragma unroll
        for (int idx = tid; idx < 128 * 8; idx += 256) {
            int r = idx >> 3, c = idx & 7;
            uint4 v = make_uint4(0u, 0u, 0u, 0u);
            if (m0 + r < M) v = ((const uint4*)Ahg)[(size_t)(m0 + r) * 32 + (kc >> 3) + c];
            ((uint4*)(As + r * G2LD))[c] = v;
        }
        {
            int r = tid >> 3, c = tid & 7;
            ((uint4*)(Bs + r * G2LD))[c] = ((const uint4*)w2t)[(size_t)r * 32 + (kc >> 3) + c];
        }
        __syncthreads();
        #pragma unroll
        for (int k = 0; k < 64; k += 16) {
            wmma::fragment<wmma::matrix_a, 16, 16, 16, __half, wmma::row_major> af[2];
            wmma::fragment<wmma::matrix_b, 16, 16, 16, __half, wmma::col_major> bf;
            wmma::load_matrix_sync(af[0], As + (wr * 32) * G2LD + k, G2LD);
            wmma::load_matrix_sync(af[1], As + (wr * 32 + 16) * G2LD + k, G2LD);
            wmma::load_matrix_sync(bf, Bs + (wc * 16) * G2LD + k, G2LD);
            wmma::mma_sync(acc[0], af[0], bf, acc[0]);
            wmma::mma_sync(acc[1], af[1], bf, acc[1]);
        }
        __syncthreads();
    }
    wmma::store_matrix_sync(Csf + (wr * 32) * 36 + wc * 16, acc[0], 36, wmma::mem_row_major);
    wmma::store_matrix_sync(Csf + (wr * 32 + 16) * 36 + wc * 16, acc[1], 36, wmma::mem_row_major);
    __syncthreads();

    int r = tid >> 1, hf = tid & 1;
    float ps = 0.f, pd = 0.f;
    #pragma unroll
    for (int j = 0; j < 4; j++) {
        float4 v = *(float4*)&Csf[r * 36 + hf * 16 + j * 4];
        float4 cs = ((const float4*)aS2)[hf * 4 + j];
        float4 cd = ((const float4*)aD2)[hf * 4 + j];
        ps += v.x * cs.x + v.y * cs.y + v.z * cs.z + v.w * cs.w;
        pd += v.x * cd.x + v.y * cd.y + v.z * cd.z + v.w * cd.w;
    }
    ps += __shfl_xor_sync(0xffffffffu, ps, 1);
    pd += __shfl_xor_sync(0xffffffffu, pd, 1);
    if (m0 + r < M) {
        if (hf == 0) { as2[m0 + r] = ps; ad2[m0 + r] = pd; }
        #pragma unroll
        for (int u = 0; u < 2; u++) {
            float4 v0 = *(float4*)&Csf[r * 36 + hf * 16 + u * 8];
            float4 v1 = *(float4*)&Csf[r * 36 + hf * 16 + u * 8 + 4];
            __half2 p0 = __floats2half2_rn(v0.x, v0.y);
            __half2 p1 = __floats2half2_rn(v0.z, v0.w);
            __half2 p2 = __floats2half2_rn(v1.x, v1.y);
            __half2 p3 = __floats2half2_rn(v1.z, v1.w);
            uint4 pk;
            pk.x = *(unsigned*)&p0; pk.y = *(unsigned*)&p1;
            pk.z = *(unsigned*)&p2; pk.w = *(unsigned*)&p3;
            *(uint4*)(h2h + (size_t)(m0 + r) * 32 + hf * 16 + u * 8) = pk;
        }
    }
}

// ---------------- merged conversions (x, W1t, W2t -> fp16) -----------------
__global__ void conv_k(const float4* __restrict__ x4, uint2* __restrict__ xh, int n4,
                       const float* __restrict__ W1, __half* __restrict__ wt,
                       const float* __restrict__ W2, __half* __restrict__ w2t) {
    int nxb = (n4 + 255) >> 8;
    int bid = blockIdx.x;
    if (bid < nxb) {
        int i = bid * 256 + threadIdx.x;
        if (i >= n4) return;
        float4 v = x4[i];
        __half2 p0 = __floats2half2_rn(v.x, v.y);
        __half2 p1 = __floats2half2_rn(v.z, v.w);
        uint2 pk;
        pk.x = *(unsigned*)&p0; pk.y = *(unsigned*)&p1;
        xh[i] = pk;
    } else if (bid < nxb + 128) {
        int i = (bid - nxb) * 256 + threadIdx.x;
        if (i >= 256 * 128) return;
        int n = i >> 7, k = i & 127;
        wt[i] = __float2half_rn(W1[k * 256 + n]);
    } else {
        int i = (bid - nxb - 128) * 256 + threadIdx.x;
        if (i >= 32 * 256) return;
        int n = i >> 8, k = i & 255;
        w2t[i] = __float2half_rn(W2[k * 32 + n]);
    }
}

// ---------------- CSR build ----------------
__global__ void init_cnt_k(int* cnt, int N) {
    int i = blockIdx.x * blockDim.x + threadIdx.x;
    if (i < N) cnt[i] = 1;
}
__global__ void hist_k(int* cnt, const int* __restrict__ dst, int E) {
    int e = blockIdx.x * blockDim.x + threadIdx.x;
    if (e < E) atomicAdd(&cnt[dst[e]], 1);
}
__global__ void scanA_k(const int* __restrict__ cnt, int* bsum, int N) {
    __shared__ int sm[256];
    int gi = blockIdx.x * 256 + threadIdx.x;
    int v = (gi < N) ? cnt[gi] : 0;
    sm[threadIdx.x] = v; __syncthreads();
    for (int off = 128; off; off >>= 1) {
        if (threadIdx.x < off) sm[threadIdx.x] += sm[threadIdx.x + off];
        __syncthreads();
    }
    if (threadIdx.x == 0) bsum[blockIdx.x] = sm[0];
}
__global__ void scanB_k(const int* __restrict__ bsum, int* boff, int nb) {
    __shared__ int sm[256];
    int t = threadIdx.x;
    int v = (t < nb) ? bsum[t] : 0;
    sm[t] = v; __syncthreads();
    #pragma unroll
    for (int off = 1; off < 256; off <<= 1) {
        int x = (t >= off) ? sm[t - off] : 0;
        __syncthreads();
        sm[t] += x;
        __syncthreads();
    }
    if (t < nb) boff[t] = sm[t] - v;
}
__global__ void scanC_k(const int* __restrict__ cnt, const int* __restrict__ boff,
                        int* row, int* cur, int N) {
    __shared__ int sm[256];
    int t = threadIdx.x;
    int gi = blockIdx.x * 256 + t;
    int v = (gi < N) ? cnt[gi] : 0;
    sm[t] = v; __syncthreads();
    #pragma unroll
    for (int off = 1; off < 256; off <<= 1) {
        int x = (t >= off) ? sm[t - off] : 0;
        __syncthreads();
        sm[t] += x;
        __syncthreads();
    }
    int excl = boff[blockIdx.x] + sm[t] - v;
    if (gi < N) { row[gi] = excl; cur[gi] = excl; }
    if (gi == N - 1) row[N] = excl + v;
}
__global__ void scatter_k(const int* __restrict__ src, const int* __restrict__ dst,
                          int* cur, int* esrc, int E, int ET) {
    int e = blockIdx.x * blockDim.x + threadIdx.x;
    if (e >= ET) return;
    int s_, d_;
    if (e < E) { s_ = src[e]; d_ = dst[e]; } else { s_ = d_ = e - E; }
    int pos = atomicAdd(&cur[d_], 1);
    esrc[pos] = s_;
}

// ---------------- fused GAT aggregate, layer 1: fp16 gather, fp16+relu out --
__global__ void gat8_k(const __half* __restrict__ h1,
                       const float* __restrict__ as, const float* __restrict__ ad,
                       const int* __restrict__ row, const int* __restrict__ esrc,
                       const float* __restrict__ bias, __half* __restrict__ outh, int N) {
    int w = (blockIdx.x * blockDim.x + threadIdx.x) >> 5;
    int l = threadIdx.x & 31;
    if (w >= N) return;
    int hgrp = l >> 2;
    int rs = row[w], re = row[w + 1];
    float adh = ad[w * 8 + hgrp];

    float mx = -3.0e38f;
    int s = esrc[rs];
    for (int i = rs; i < re; i++) {
        int sn = (i + 1 < re) ? esrc[i + 1] : 0;
        float v = lrelu(__ldg(as + s * 8 + hgrp) + adh);
        mx = fmaxf(mx, v);
        s = sn;
    }
    float sum = 0.f;
    float acc[8] = {};
    s = esrc[rs];
    for (int i = rs; i < re; i++) {
        int sn = (i + 1 < re) ? esrc[i + 1] : 0;
        float v = lrelu(__ldg(as + s * 8 + hgrp) + adh);
        float ex = expf(v - mx);
        sum += ex;
        uint4 raw = ((const uint4*)(h1 + (size_t)s * 256))[l];
        __half2* hh = (__half2*)&raw;
        float2 f0 = __half22float2(hh[0]);
        float2 f1 = __half22float2(hh[1]);
        float2 f2 = __half22float2(hh[2]);
        float2 f3 = __half22float2(hh[3]);
        acc[0] += ex * f0.x; acc[1] += ex * f0.y;
        acc[2] += ex * f1.x; acc[3] += ex * f1.y;
        acc[4] += ex * f2.x; acc[5] += ex * f2.y;
        acc[6] += ex * f3.x; acc[7] += ex * f3.y;
        s = sn;
    }
    float inv = 1.f / (sum + 1e-16f);
    float4 b0 = ((const float4*)bias)[2 * l];
    float4 b1 = ((const float4*)bias)[2 * l + 1];
    float o[8];
    o[0] = fmaxf(acc[0] * inv + b0.x, 0.f); o[1] = fmaxf(acc[1] * inv + b0.y, 0.f);
    o[2] = fmaxf(acc[2] * inv + b0.z, 0.f); o[3] = fmaxf(acc[3] * inv + b0.w, 0.f);
    o[4] = fmaxf(acc[4] * inv + b1.x, 0.f); o[5] = fmaxf(acc[5] * inv + b1.y, 0.f);
    o[6] = fmaxf(acc[6] * inv + b1.z, 0.f); o[7] = fmaxf(acc[7] * inv + b1.w, 0.f);
    __half2 p0 = __floats2half2_rn(o[0], o[1]);
    __half2 p1 = __floats2half2_rn(o[2], o[3]);
    __half2 p2 = __floats2half2_rn(o[4], o[5]);
    __half2 p3 = __floats2half2_rn(o[6], o[7]);
    uint4 pk;
    pk.x = *(unsigned*)&p0; pk.y = *(unsigned*)&p1;
    pk.z = *(unsigned*)&p2; pk.w = *(unsigned*)&p3;
    *(uint4*)(outh + (size_t)w * 256 + 8 * l) = pk;
}

// ------- fused GAT layer 2 + decoder: warp per dst, z stays in registers ----
// out[w][:] = (softmax-agg h2)[w] @ Wd + bd  (z never hits gmem; fp32 exact)
__global__ void gat1_dec_k(const __half* __restrict__ h2,
                           const float* __restrict__ as, const float* __restrict__ ad,
                           const int* __restrict__ row, const int* __restrict__ esrc,
                           const float* __restrict__ b2,
                           const float* __restrict__ Wd, const float* __restrict__ bd,
                           float* __restrict__ out, int N) {
    __shared__ float4 Wds[32 * 32];   // Wd[l][c4]: float4 covering cols 4c4..4c4+3
    __shared__ float4 bds[32];
    int tid = threadIdx.x;
    int l = tid & 31;
    // stage Wd (32x128 fp32 = 16KB) + bd
    for (int i = tid; i < 32 * 32; i += blockDim.x)
        Wds[i] = ((const float4*)Wd)[i];
    for (int i = tid; i < 32; i += blockDim.x)
        bds[i] = ((const float4*)bd)[i];
    __syncthreads();

    int w = (blockIdx.x * blockDim.x + tid) >> 5;
    if (w >= N) return;
    int rs = row[w], re = row[w + 1];
    float adh = ad[w];

    float mx = -3.0e38f;
    int s = esrc[rs];
    for (int i = rs; i < re; i++) {
        int sn = (i + 1 < re) ? esrc[i + 1] : 0;
        float v = lrelu(__ldg(as + s) + adh);
        mx = fmaxf(mx, v);
        s = sn;
    }
    float sum = 0.f, acc = 0.f;
    s = esrc[rs];
    for (int i = rs; i < re; i++) {
        int sn = (i + 1 < re) ? esrc[i + 1] : 0;
        float v = lrelu(__ldg(as + s) + adh);
        float ex = expf(v - mx);
        sum += ex;
        acc += ex * __half2float(__ldg(h2 + (size_t)s * 32 + l));
        s = sn;
    }
    float zl = acc / (sum + 1e-16f) + b2[l];   // z[w][l], fp32

    // decoder: each lane computes output cols 4l..4l+3
    float4 oacc = bds[l];
    #pragma unroll
    for (int k = 0; k < 32; k++) {
        float zb = __shfl_sync(0xffffffffu, zl, k);
        float4 wv = Wds[k * 32 + l];
        oacc.x += zb * wv.x; oacc.y += zb * wv.y;
        oacc.z += zb * wv.z; oacc.w += zb * wv.w;
    }
    *(float4*)(out + (size_t)w * 128 + 4 * l) = oacc;
}

// ---------------- launch ----------------
extern "C" void kernel_launch(void* const* d_in, const int* in_sizes, int n_in,
                              void* d_out, int out_size) {
    const float* x   = (const float*)d_in[0];
    const int*   ei  = (const int*)d_in[1];
    const float* W1  = (const float*)d_in[2];
    const float* aS1 = (const float*)d_in[3];
    const float* aD1 = (const float*)d_in[4];
    const float* b1  = (const float*)d_in[5];
    const float* W2  = (const float*)d_in[6];
    const float* aS2 = (const float*)d_in[7];
    const float* aD2 = (const float*)d_in[8];
    const float* b2  = (const float*)d_in[9];
    const float* Wd  = (const float*)d_in[10];
    const float* bd  = (const float*)d_in[11];
    float* out = (float*)d_out;

    int N  = in_sizes[0] / 128;
    int E  = in_sizes[1] / 2;
    int ET = E + N;
    const int* src = ei;
    const int* dst = ei + E;

    float *as1, *ad1, *as2, *ad2;
    __half *h1h, *o1h, *h2h, *xh, *wth, *w2t;
    int *cnt, *row, *cur, *bsum, *boff, *esrc;
    cudaGetSymbolAddress((void**)&h1h,  g_h1h);
    cudaGetSymbolAddress((void**)&o1h,  g_o1h);
    cudaGetSymbolAddress((void**)&as1,  g_as1);
    cudaGetSymbolAddress((void**)&ad1,  g_ad1);
    cudaGetSymbolAddress((void**)&h2h,  g_h2h);
    cudaGetSymbolAddress((void**)&as2,  g_as2);
    cudaGetSymbolAddress((void**)&ad2,  g_ad2);
    cudaGetSymbolAddress((void**)&cnt,  g_cnt);
    cudaGetSymbolAddress((void**)&row,  g_row);
    cudaGetSymbolAddress((void**)&cur,  g_cur);
    cudaGetSymbolAddress((void**)&bsum, g_bsum);
    cudaGetSymbolAddress((void**)&boff, g_boff);
    cudaGetSymbolAddress((void**)&esrc, g_esrc);
    cudaGetSymbolAddress((void**)&xh,   g_xh);
    cudaGetSymbolAddress((void**)&wth,  g_wth);
    cudaGetSymbolAddress((void**)&w2t,  g_w2t);

    cudaFuncSetAttribute(gemm1_wmma_k, cudaFuncAttributeMaxDynamicSharedMemorySize, WSM_TOTAL);

    const int TB = 256;
    int mb = (N + 127) / 128;
    int nb = (N + 255) / 256;
    int n4 = N * 32;
    int nxb = (n4 + 255) / 256;

    init_cnt_k<<<nb, TB>>>(cnt, N);                                    // 1
    hist_k<<<(E + TB - 1) / TB, TB>>>(cnt, dst, E);                    // 2
    conv_k<<<nxb + 128 + 32, TB>>>((const float4*)x, (uint2*)xh, n4,
                                   W1, wth, W2, w2t);                  // 3
    gemm1_wmma_k<<<dim3(2, mb), 512, WSM_TOTAL>>>(xh, wth, aS1, aD1,
                                                  h1h, as1, ad1, N);   // 4 (profiled)
    scanA_k<<<nb, TB>>>(cnt, bsum, N);                                 // 5
    scanB_k<<<1, TB>>>(bsum, boff, nb);                                // 6
    scanC_k<<<nb, TB>>>(cnt, boff, row, cur, N);                       // 7
    scatter_k<<<(ET + TB - 1) / TB, TB>>>(src, dst, cur, esrc, E, ET); // 8

    // ===== Layer 1 aggregate (fp16 gather, fp16+relu out) =====
    gat8_k<<<(N * 32 + TB - 1) / TB, TB>>>(h1h, as1, ad1, row, esrc, b1, o1h, N); // 9

    // ===== Layer 2 GEMM (alpha1 fused, fp16 out) =====
    gemm2_wmma_k<<<mb, TB>>>(o1h, w2t, aS2, aD2, h2h, as2, ad2, N);    // 10

    // ===== Layer 2 aggregate + decoder fused (z stays in registers) =====
    gat1_dec_k<<<(N * 32 + TB - 1) / TB, TB>>>(h2h, as2, ad2, row, esrc,
                                               b2, Wd, bd, out, N);    // 11
}